// round 5
// baseline (speedup 1.0000x reference)
#include <cuda_runtime.h>
#include <cuda_bf16.h>

#define R_     512
#define C_     256
#define H_     200
#define W_     200
#define OUTK   7
#define HW_    (H_*W_)
#define CHUNK  32   // channels per block
#define ROWMAX 28   // max patch rows (max tap span <= 26)

// ---------------------------------------------------------------------------
// One block per (roi, channel-chunk). Grid (512, 8), chunk slowest so the
// per-phase working set (all-roi coverage x 32 ch ~ 17 MB) stays L2-resident.
//
// Phase 1: warp 0 builds the 28-entry x-tap table, warp 1 builds the
// 28-entry y-tap table (all 7 oy bins). ALL 32 lanes of each warp stay
// convergent (lanes 28..31 compute a dummy tap, writes guarded), so the
// full-mask shfl min/max row-range reduction in warp 1 is safe.
//
// Phase 2 (x-reduce): warp w owns channels {w, w+8, w+16, w+24}. Each unique
// patch row is loaded ONCE per channel (vs 28 row-loads/channel in the R3
// kernel): lanes = x-taps, weighted load, 4-lane shfl reduce, lanes
// {0,4,..,24} store 7 x-pooled values to xred[c][row][.].
//
// Phase 3 (y-reduce): 1568 outputs; each thread combines 4 y-taps from xred.
// ---------------------------------------------------------------------------
__global__ __launch_bounds__(256) void roialign_kernel(
    const float* __restrict__ feat, const float* __restrict__ rois,
    float* __restrict__ out)
{
    int r   = blockIdx.x;
    int ch0 = blockIdx.y * CHUNK;

    __shared__ int   s_xi[28];
    __shared__ float s_xw[28];
    __shared__ int   s_yi[28];
    __shared__ float s_yw[28];
    __shared__ int   s_rmin, s_boff;
    __shared__ float xred[CHUNK * ROWMAX * 8];  // [c][row][ox(pad 8)]

    int tid  = threadIdx.x;
    int lane = tid & 31;
    int warp = tid >> 5;

    if (warp < 2) {                       // fully convergent per warp
        const float* ro = rois + r * 5;
        bool isx = (warp == 0);
        float p1 = (isx ? ro[1] : ro[2]) * 0.25f;
        float p2 = (isx ? ro[3] : ro[4]) * 0.25f;
        float bin = fmaxf(p2 - p1, 1.0f) * (1.0f / (float)OUTK);

        int t   = min(lane, 27);          // lanes 28..31: dummy tap 27
        int o   = t >> 2;
        int s   = (t >> 1) & 1;
        int tap = t & 1;
        float y = p1 + ((float)o + ((float)s + 0.5f) * 0.5f) * bin;
        bool valid = (y >= -1.0f) && (y <= 200.0f);
        float yc = fminf(fmaxf(y, 0.0f), 199.0f);
        int   yl = (int)floorf(yc);
        int   yh = min(yl + 1, 199);
        float fl = yc - (float)yl;
        float wv = tap ? fl : (1.0f - fl);
        if (!valid) wv = 0.0f;
        int   iv = tap ? yh : yl;

        if (lane < 28) {
            if (isx) { s_xi[lane] = iv; s_xw[lane] = wv; }
            else     { s_yi[lane] = iv; s_yw[lane] = wv; }
        }
        if (!isx) {
            // min over y-tap indices, all 32 lanes participate
            int vmin = (lane < 28) ? iv : 10000;
            #pragma unroll
            for (int d = 16; d; d >>= 1)
                vmin = min(vmin, __shfl_xor_sync(0xffffffffu, vmin, d));
            if (lane == 0) s_rmin = vmin;
        }
        if (tid == 0) s_boff = (int)ro[0] * (C_ * HW_);
    }
    __syncthreads();

    // ---- Phase 2: x-reduction, one pass over unique patch rows ----
    int l    = min(lane, 27);
    int xi   = s_xi[l];
    float xw = s_xw[l];
    int rmin = s_rmin;
    // row count: recompute max locally from shared y-tap table (cheap, uniform)
    int rmax = 0;
    #pragma unroll
    for (int j = 0; j < 28; j += 4)      // tap index 1 (yh of sample 0) grows
        rmax = max(rmax, s_yi[j + 3]);   // last tap of each bin is largest
    rmax = max(rmax, s_yi[27]);
    int rcnt = rmax - rmin + 1;

    const float* fb = feat + s_boff + (size_t)(ch0 + warp) * HW_;
    bool doStore = (lane < 28) && ((lane & 3) == 0);
    int  ox      = l >> 2;

    for (int rowi = 0; rowi < rcnt; rowi++) {
        int base = (rmin + rowi) * W_ + xi;
        float v0 = __ldg(fb + base);
        float v1 = __ldg(fb +  8 * HW_ + base);
        float v2 = __ldg(fb + 16 * HW_ + base);
        float v3 = __ldg(fb + 24 * HW_ + base);
        v0 *= xw; v1 *= xw; v2 *= xw; v3 *= xw;
        v0 += __shfl_xor_sync(0xffffffffu, v0, 1);
        v1 += __shfl_xor_sync(0xffffffffu, v1, 1);
        v2 += __shfl_xor_sync(0xffffffffu, v2, 1);
        v3 += __shfl_xor_sync(0xffffffffu, v3, 1);
        v0 += __shfl_xor_sync(0xffffffffu, v0, 2);
        v1 += __shfl_xor_sync(0xffffffffu, v1, 2);
        v2 += __shfl_xor_sync(0xffffffffu, v2, 2);
        v3 += __shfl_xor_sync(0xffffffffu, v3, 2);
        if (doStore) {
            xred[((warp     ) * ROWMAX + rowi) * 8 + ox] = v0;
            xred[((warp +  8) * ROWMAX + rowi) * 8 + ox] = v1;
            xred[((warp + 16) * ROWMAX + rowi) * 8 + ox] = v2;
            xred[((warp + 24) * ROWMAX + rowi) * 8 + ox] = v3;
        }
    }
    __syncthreads();

    // ---- Phase 3: y-reduction + store ----
    float* ob = out + ((size_t)r * C_ + ch0) * (OUTK * OUTK);
    #pragma unroll
    for (int i = 0; i < (CHUNK * OUTK * OUTK + 255) / 256; i++) {
        int idx = tid + i * 256;
        if (idx < CHUNK * OUTK * OUTK) {
            int c   = idx / (OUTK * OUTK);
            int pos = idx - c * (OUTK * OUTK);
            int oyy = pos / OUTK;
            int oxx = pos - oyy * OUTK;
            float acc = 0.0f;
            #pragma unroll
            for (int j = 0; j < 4; j++) {
                int   row = s_yi[oyy * 4 + j] - rmin;
                float w   = s_yw[oyy * 4 + j];
                acc += w * xred[(c * ROWMAX + row) * 8 + oxx];
            }
            ob[idx] = acc * 0.25f;
        }
    }
}

extern "C" void kernel_launch(void* const* d_in, const int* in_sizes, int n_in,
                              void* d_out, int out_size) {
    const float* feat = (const float*)d_in[0];
    const float* rois = (const float*)d_in[1];
    if (n_in >= 2 && in_sizes[0] == R_ * 5) {  // defensive against input order
        feat = (const float*)d_in[1];
        rois = (const float*)d_in[0];
    }
    float* out = (float*)d_out;

    dim3 grid(R_, C_ / CHUNK);   // chunk (y) slowest -> L2 phase blocking
    roialign_kernel<<<grid, 256>>>(feat, rois, out);
}

// round 6
// speedup vs baseline: 1.1008x; 1.1008x over previous
#include <cuda_runtime.h>
#include <cuda_bf16.h>

#define R_    512
#define C_    256
#define H_    200
#define W_    200
#define OUTK  7
#define HW_   (H_*W_)
#define CHUNK 32   // channels per block (grid.z = C_/CHUNK phases, z slowest)

// ---------------------------------------------------------------------------
// Grid: (7, 512, 8) = (out_y, roi, channel-chunk), z slowest -> per-phase
// feature working set (~17 MB) stays L2-resident (R3-proven: 157 MB DRAM).
//
// Phase 1 (threads 0..31): bilinear tap tables for this (roi, oy) from rois.
// Phase 2: lane -> (out_x, x-tap): lane = ox*4 + jx (lanes 28..31 duplicate
// lane 27, never store). Each warp covers its 4 chunk channels
// {w, w+8, w+16, w+24} in ONE iteration structure: all 16 LDGs issued
// back-to-back (front-batched MLP=16) before any FMA/shfl/store.
// ---------------------------------------------------------------------------
__global__ __launch_bounds__(256) void roialign_kernel(
    const float* __restrict__ feat, const float* __restrict__ rois,
    float* __restrict__ out)
{
    int oy  = blockIdx.x;
    int r   = blockIdx.y;
    int ch0 = blockIdx.z * CHUNK;

    __shared__ int   s_xi[28];
    __shared__ float s_xw[28];
    __shared__ int   s_yi[4];
    __shared__ float s_yw[4];
    __shared__ int   s_boff;

    int tid = threadIdx.x;
    if (tid < 32) {
        const float* ro = rois + r * 5;
        bool isx = tid < 28;
        float p1 = (isx ? ro[1] : ro[2]) * 0.25f;
        float p2 = (isx ? ro[3] : ro[4]) * 0.25f;
        float bin = fmaxf(p2 - p1, 1.0f) * (1.0f / (float)OUTK);

        int o, s, tap;
        if (isx) { o = tid >> 2; s = (tid >> 1) & 1; tap = tid & 1; }
        else     { int t = tid - 28; o = oy; s = t >> 1; tap = t & 1; }

        float y = p1 + ((float)o + ((float)s + 0.5f) * 0.5f) * bin;
        bool valid = (y >= -1.0f) && (y <= 200.0f);
        float yc = fminf(fmaxf(y, 0.0f), 199.0f);
        int   yl = (int)floorf(yc);
        int   yh = min(yl + 1, 199);
        float l  = yc - (float)yl;
        float wv = tap ? l : (1.0f - l);
        if (!valid) wv = 0.0f;
        int   iv = tap ? yh : yl;

        if (isx) { s_xi[tid] = iv; s_xw[tid] = wv; }
        else     { s_yi[tid - 28] = iv; s_yw[tid - 28] = wv; }
        if (tid == 0) s_boff = (int)ro[0] * (C_ * HW_);
    }
    __syncthreads();

    int lane = tid & 31;
    int warp = tid >> 5;
    int l    = min(lane, 27);

    int   xi = s_xi[l];
    float xw = s_xw[l];
    float yw0 = s_yw[0], yw1 = s_yw[1], yw2 = s_yw[2], yw3 = s_yw[3];
    int off0 = s_yi[0] * W_ + xi;
    int off1 = s_yi[1] * W_ + xi;
    int off2 = s_yi[2] * W_ + xi;
    int off3 = s_yi[3] * W_ + xi;

    // 4 channel base pointers for this warp (c = warp + {0,8,16,24} of chunk)
    const float* f0 = feat + s_boff + (size_t)(ch0 + warp) * HW_;
    const float* f1 = f0 +  8 * HW_;
    const float* f2 = f0 + 16 * HW_;
    const float* f3 = f0 + 24 * HW_;

    int  ox      = l >> 2;
    bool doStore = (lane < 28) && ((lane & 3) == 0);
    float* orow  = out + (((size_t)r * C_ + ch0 + warp) * OUTK + oy) * OUTK + ox;

    // ---- 16 LDGs issued back-to-back (front-batched MLP) ----
    float a00 = __ldg(f0 + off0), a01 = __ldg(f0 + off1),
          a02 = __ldg(f0 + off2), a03 = __ldg(f0 + off3);
    float a10 = __ldg(f1 + off0), a11 = __ldg(f1 + off1),
          a12 = __ldg(f1 + off2), a13 = __ldg(f1 + off3);
    float a20 = __ldg(f2 + off0), a21 = __ldg(f2 + off1),
          a22 = __ldg(f2 + off2), a23 = __ldg(f2 + off3);
    float a30 = __ldg(f3 + off0), a31 = __ldg(f3 + off1),
          a32 = __ldg(f3 + off2), a33 = __ldg(f3 + off3);

    float b0 = (yw0 * a00 + yw1 * a01 + yw2 * a02 + yw3 * a03) * xw;
    float b1 = (yw0 * a10 + yw1 * a11 + yw2 * a12 + yw3 * a13) * xw;
    float b2 = (yw0 * a20 + yw1 * a21 + yw2 * a22 + yw3 * a23) * xw;
    float b3 = (yw0 * a30 + yw1 * a31 + yw2 * a32 + yw3 * a33) * xw;

    b0 += __shfl_xor_sync(0xffffffffu, b0, 1);
    b1 += __shfl_xor_sync(0xffffffffu, b1, 1);
    b2 += __shfl_xor_sync(0xffffffffu, b2, 1);
    b3 += __shfl_xor_sync(0xffffffffu, b3, 1);
    b0 += __shfl_xor_sync(0xffffffffu, b0, 2);
    b1 += __shfl_xor_sync(0xffffffffu, b1, 2);
    b2 += __shfl_xor_sync(0xffffffffu, b2, 2);
    b3 += __shfl_xor_sync(0xffffffffu, b3, 2);

    if (doStore) {
        orow[0]                        = b0 * 0.25f;
        orow[ 8 * (OUTK * OUTK)]       = b1 * 0.25f;
        orow[16 * (OUTK * OUTK)]       = b2 * 0.25f;
        orow[24 * (OUTK * OUTK)]       = b3 * 0.25f;
    }
}

extern "C" void kernel_launch(void* const* d_in, const int* in_sizes, int n_in,
                              void* d_out, int out_size) {
    const float* feat = (const float*)d_in[0];
    const float* rois = (const float*)d_in[1];
    if (n_in >= 2 && in_sizes[0] == R_ * 5) {  // defensive against input order
        feat = (const float*)d_in[1];
        rois = (const float*)d_in[0];
    }
    float* out = (float*)d_out;

    dim3 grid(OUTK, R_, C_ / CHUNK);
    roialign_kernel<<<grid, 256>>>(feat, rois, out);
}

// round 7
// speedup vs baseline: 1.1441x; 1.0393x over previous
#include <cuda_runtime.h>
#include <cuda_bf16.h>

#define R_    512
#define C_    256
#define H_    200
#define W_    200
#define OUTK  7
#define HW_   (H_*W_)
#define CHUNK 32   // channels per block (grid.z = C_/CHUNK phases, z slowest)

// ---------------------------------------------------------------------------
// Grid: (7, 512, 8) = (out_y, roi, channel-chunk), z slowest -> per-phase
// feature working set (~17 MB) stays L2-resident (proven: 157 MB DRAM).
//
// Key change vs R6: the 4 y-taps {yl0, yh0, yl1, yh1} lie in the contiguous
// row span [yl0 .. yh1] of width rcnt in [1,4] (avg ~3, since yh0 == yl1
// typically). We fold the 4 tap weights into a dense weight vector dw[0..3]
// over that span and load each row ONCE: 4 -> rcnt row-loads per
// (roi, ch, oy), i.e. ~25% fewer LDGs/L1 wavefronts, no SMEM traffic added.
// rcnt is uniform across the block -> uniform branch to unrolled bodies.
// ---------------------------------------------------------------------------

template<int K>
__device__ __forceinline__ void accum4(
    const float* __restrict__ f0, const float* __restrict__ f1,
    const float* __restrict__ f2, const float* __restrict__ f3,
    const int off[4], const float dw[4],
    float& b0, float& b1, float& b2, float& b3)
{
    float v0[K], v1[K], v2[K], v3[K];
    #pragma unroll
    for (int j = 0; j < K; j++) {
        v0[j] = __ldg(f0 + off[j]);
        v1[j] = __ldg(f1 + off[j]);
        v2[j] = __ldg(f2 + off[j]);
        v3[j] = __ldg(f3 + off[j]);
    }
    b0 = 0.f; b1 = 0.f; b2 = 0.f; b3 = 0.f;
    #pragma unroll
    for (int j = 0; j < K; j++) {
        b0 += dw[j] * v0[j];
        b1 += dw[j] * v1[j];
        b2 += dw[j] * v2[j];
        b3 += dw[j] * v3[j];
    }
}

__global__ __launch_bounds__(256) void roialign_kernel(
    const float* __restrict__ feat, const float* __restrict__ rois,
    float* __restrict__ out)
{
    int oy  = blockIdx.x;
    int r   = blockIdx.y;
    int ch0 = blockIdx.z * CHUNK;

    __shared__ int   s_xi[28];
    __shared__ float s_xw[28];
    __shared__ int   s_yi[4];
    __shared__ float s_yw[4];
    __shared__ int   s_boff;

    int tid = threadIdx.x;
    if (tid < 32) {
        const float* ro = rois + r * 5;
        bool isx = tid < 28;
        float p1 = (isx ? ro[1] : ro[2]) * 0.25f;
        float p2 = (isx ? ro[3] : ro[4]) * 0.25f;
        float bin = fmaxf(p2 - p1, 1.0f) * (1.0f / (float)OUTK);

        int o, s, tap;
        if (isx) { o = tid >> 2; s = (tid >> 1) & 1; tap = tid & 1; }
        else     { int t = tid - 28; o = oy; s = t >> 1; tap = t & 1; }

        float y = p1 + ((float)o + ((float)s + 0.5f) * 0.5f) * bin;
        bool valid = (y >= -1.0f) && (y <= 200.0f);
        float yc = fminf(fmaxf(y, 0.0f), 199.0f);
        int   yl = (int)floorf(yc);
        int   yh = min(yl + 1, 199);
        float l  = yc - (float)yl;
        float wv = tap ? l : (1.0f - l);
        if (!valid) wv = 0.0f;
        int   iv = tap ? yh : yl;

        if (isx) { s_xi[tid] = iv; s_xw[tid] = wv; }
        else     { s_yi[tid - 28] = iv; s_yw[tid - 28] = wv; }
        if (tid == 0) s_boff = (int)ro[0] * (C_ * HW_);
    }
    __syncthreads();

    int lane = tid & 31;
    int warp = tid >> 5;
    int l    = min(lane, 27);

    int   xi = s_xi[l];
    float xw = s_xw[l];

    // Dense y-weights over the contiguous row span [rbase .. rbase+rcnt-1].
    // s_yi is sorted: yl(s0) <= yh(s0), yl(s1) <= yh(s1), yl(s0) <= yl(s1),
    // so rbase = s_yi[0] is min and s_yi[3] is max.
    int rbase = s_yi[0];
    int rcnt  = s_yi[3] - rbase + 1;           // 1..4, uniform across block
    float dw[4] = {0.f, 0.f, 0.f, 0.f};
    #pragma unroll
    for (int k = 0; k < 4; k++) {
        int   d = s_yi[k] - rbase;
        float w = s_yw[k];
        #pragma unroll
        for (int j = 0; j < 4; j++)
            dw[j] += (d == j) ? w : 0.f;
    }
    int off[4];
    #pragma unroll
    for (int j = 0; j < 4; j++)
        off[j] = (rbase + j) * W_ + xi;

    const float* f0 = feat + s_boff + (size_t)(ch0 + warp) * HW_;
    const float* f1 = f0 +  8 * HW_;
    const float* f2 = f0 + 16 * HW_;
    const float* f3 = f0 + 24 * HW_;

    int  ox      = l >> 2;
    bool doStore = (lane < 28) && ((lane & 3) == 0);
    float* orow  = out + (((size_t)r * C_ + ch0 + warp) * OUTK + oy) * OUTK + ox;

    float b0, b1, b2, b3;
    switch (rcnt) {                            // uniform per block
        case 1:  accum4<1>(f0, f1, f2, f3, off, dw, b0, b1, b2, b3); break;
        case 2:  accum4<2>(f0, f1, f2, f3, off, dw, b0, b1, b2, b3); break;
        case 3:  accum4<3>(f0, f1, f2, f3, off, dw, b0, b1, b2, b3); break;
        default: accum4<4>(f0, f1, f2, f3, off, dw, b0, b1, b2, b3); break;
    }

    b0 *= xw; b1 *= xw; b2 *= xw; b3 *= xw;
    b0 += __shfl_xor_sync(0xffffffffu, b0, 1);
    b1 += __shfl_xor_sync(0xffffffffu, b1, 1);
    b2 += __shfl_xor_sync(0xffffffffu, b2, 1);
    b3 += __shfl_xor_sync(0xffffffffu, b3, 1);
    b0 += __shfl_xor_sync(0xffffffffu, b0, 2);
    b1 += __shfl_xor_sync(0xffffffffu, b1, 2);
    b2 += __shfl_xor_sync(0xffffffffu, b2, 2);
    b3 += __shfl_xor_sync(0xffffffffu, b3, 2);

    if (doStore) {
        orow[0]                  = b0 * 0.25f;
        orow[ 8 * (OUTK * OUTK)] = b1 * 0.25f;
        orow[16 * (OUTK * OUTK)] = b2 * 0.25f;
        orow[24 * (OUTK * OUTK)] = b3 * 0.25f;
    }
}

extern "C" void kernel_launch(void* const* d_in, const int* in_sizes, int n_in,
                              void* d_out, int out_size) {
    const float* feat = (const float*)d_in[0];
    const float* rois = (const float*)d_in[1];
    if (n_in >= 2 && in_sizes[0] == R_ * 5) {  // defensive against input order
        feat = (const float*)d_in[1];
        rois = (const float*)d_in[0];
    }
    float* out = (float*)d_out;

    dim3 grid(OUTK, R_, C_ / CHUNK);
    roialign_kernel<<<grid, 256>>>(feat, rois, out);
}

// round 8
// speedup vs baseline: 1.2888x; 1.1265x over previous
#include <cuda_runtime.h>
#include <cuda_bf16.h>

#define R_    512
#define C_    256
#define H_    200
#define W_    200
#define OUTK  7
#define HW_   (H_*W_)
#define CHUNK 64   // channels per block (grid.z = C_/CHUNK phases, z slowest)

// ---------------------------------------------------------------------------
// Grid: (7, 512, 4) = (out_y, roi, channel-chunk), z slowest -> per-phase
// feature working set (~34 MB) stays L2-resident (DRAM traffic ~157 MB).
//
// Phase 1 (warp 0): builds x-tap table (lanes 0..27) and y-taps (lanes
// 28..31), then broadcasts the 4 y-taps via shfl and computes the DENSE
// y-weight vector dw[4] over the contiguous row span [rbase..rbase+rcnt-1]
// ONCE (lane 0 writes to SMEM) — R7 computed this redundantly in all 256
// threads (ALU 33%).
//
// Phase 2: lane -> (out_x, x-tap): lane = ox*4 + jx. Each warp covers 8
// channels {w + 8k} of the 64-channel chunk (2 groups of 4), loading each
// span row once per channel. 4-lane shfl reduce; lanes {0,4,..,24} store.
// ---------------------------------------------------------------------------

template<int K>
__device__ __forceinline__ void accum4(
    const float* __restrict__ fb, const int off[4], const float dw[4],
    float& b0, float& b1, float& b2, float& b3)
{
    const float* f1 = fb +  8 * HW_;
    const float* f2 = fb + 16 * HW_;
    const float* f3 = fb + 24 * HW_;
    float v0[K], v1[K], v2[K], v3[K];
    #pragma unroll
    for (int j = 0; j < K; j++) {
        v0[j] = __ldg(fb + off[j]);
        v1[j] = __ldg(f1 + off[j]);
        v2[j] = __ldg(f2 + off[j]);
        v3[j] = __ldg(f3 + off[j]);
    }
    b0 = 0.f; b1 = 0.f; b2 = 0.f; b3 = 0.f;
    #pragma unroll
    for (int j = 0; j < K; j++) {
        b0 += dw[j] * v0[j];
        b1 += dw[j] * v1[j];
        b2 += dw[j] * v2[j];
        b3 += dw[j] * v3[j];
    }
}

template<int K>
__device__ __forceinline__ void do_group(
    const float* __restrict__ fb, const int off[4], const float dw[4],
    float xw, bool doStore, float* __restrict__ orow)
{
    float b0, b1, b2, b3;
    accum4<K>(fb, off, dw, b0, b1, b2, b3);
    b0 *= xw; b1 *= xw; b2 *= xw; b3 *= xw;
    b0 += __shfl_xor_sync(0xffffffffu, b0, 1);
    b1 += __shfl_xor_sync(0xffffffffu, b1, 1);
    b2 += __shfl_xor_sync(0xffffffffu, b2, 1);
    b3 += __shfl_xor_sync(0xffffffffu, b3, 1);
    b0 += __shfl_xor_sync(0xffffffffu, b0, 2);
    b1 += __shfl_xor_sync(0xffffffffu, b1, 2);
    b2 += __shfl_xor_sync(0xffffffffu, b2, 2);
    b3 += __shfl_xor_sync(0xffffffffu, b3, 2);
    if (doStore) {
        orow[0]                  = b0;
        orow[ 8 * (OUTK * OUTK)] = b1;
        orow[16 * (OUTK * OUTK)] = b2;
        orow[24 * (OUTK * OUTK)] = b3;
    }
}

__global__ __launch_bounds__(256) void roialign_kernel(
    const float* __restrict__ feat, const float* __restrict__ rois,
    float* __restrict__ out)
{
    int oy  = blockIdx.x;
    int r   = blockIdx.y;
    int ch0 = blockIdx.z * CHUNK;

    __shared__ int   s_xi[28];
    __shared__ float s_xw[28];
    __shared__ float s_dw[4];
    __shared__ int   s_rbase, s_rcnt, s_boff;

    int tid = threadIdx.x;
    if (tid < 32) {                       // warp 0, fully convergent
        const float* ro = rois + r * 5;
        bool isx = tid < 28;
        float p1 = (isx ? ro[1] : ro[2]) * 0.25f;
        float p2 = (isx ? ro[3] : ro[4]) * 0.25f;
        float bin = fmaxf(p2 - p1, 1.0f) * (1.0f / (float)OUTK);

        int o, s, tap;
        if (isx) { o = tid >> 2; s = (tid >> 1) & 1; tap = tid & 1; }
        else     { int t = tid - 28; o = oy; s = t >> 1; tap = t & 1; }

        float y = p1 + ((float)o + ((float)s + 0.5f) * 0.5f) * bin;
        bool valid = (y >= -1.0f) && (y <= 200.0f);
        float yc = fminf(fmaxf(y, 0.0f), 199.0f);
        int   yl = (int)floorf(yc);
        int   yh = min(yl + 1, 199);
        float l  = yc - (float)yl;
        float wv = tap ? l : (1.0f - l);
        if (!valid) wv = 0.0f;
        int   iv = tap ? yh : yl;

        if (isx) { s_xi[tid] = iv; s_xw[tid] = wv; }

        // Broadcast the 4 y-taps (lanes 28..31) to all lanes; compute dense
        // weights once. Taps sorted: lane28=yl0 (min) .. lane31=yh1 (max).
        int   yi0 = __shfl_sync(0xffffffffu, iv, 28);
        int   yi1 = __shfl_sync(0xffffffffu, iv, 29);
        int   yi2 = __shfl_sync(0xffffffffu, iv, 30);
        int   yi3 = __shfl_sync(0xffffffffu, iv, 31);
        float yw0 = __shfl_sync(0xffffffffu, wv, 28);
        float yw1 = __shfl_sync(0xffffffffu, wv, 29);
        float yw2 = __shfl_sync(0xffffffffu, wv, 30);
        float yw3 = __shfl_sync(0xffffffffu, wv, 31);
        if (tid == 0) {
            float dw[4] = {0.f, 0.f, 0.f, 0.f};
            dw[0] += yw0;                       // yi0 == rbase
            dw[yi1 - yi0] += yw1;
            dw[yi2 - yi0] += yw2;
            dw[yi3 - yi0] += yw3;
            s_dw[0] = dw[0]; s_dw[1] = dw[1];
            s_dw[2] = dw[2]; s_dw[3] = dw[3];
            s_rbase = yi0;
            s_rcnt  = yi3 - yi0 + 1;
            s_boff  = (int)ro[0] * (C_ * HW_);
        }
    }
    __syncthreads();

    int lane = tid & 31;
    int warp = tid >> 5;
    int l    = min(lane, 27);

    int   xi = s_xi[l];
    float xw = s_xw[l] * 0.25f;           // fold the S*S mean here
    float dw[4] = { s_dw[0], s_dw[1], s_dw[2], s_dw[3] };
    int rbase = s_rbase;
    int rcnt  = s_rcnt;
    int off[4];
    #pragma unroll
    for (int j = 0; j < 4; j++)
        off[j] = (rbase + j) * W_ + xi;

    const float* fb = feat + s_boff + (size_t)(ch0 + warp) * HW_;
    int  ox      = l >> 2;
    bool doStore = (lane < 28) && ((lane & 3) == 0);
    float* orow  = out + (((size_t)r * C_ + ch0 + warp) * OUTK + oy) * OUTK + ox;

    // 8 channels per warp: two 4-channel groups (c = warp + {0,8,16,24} and
    // + {32,40,48,56}), reusing the shared setup.
    switch (rcnt) {                       // uniform per block
        case 1:
            do_group<1>(fb, off, dw, xw, doStore, orow);
            do_group<1>(fb + 32 * HW_, off, dw, xw, doStore,
                        orow + (size_t)32 * OUTK * OUTK);
            break;
        case 2:
            do_group<2>(fb, off, dw, xw, doStore, orow);
            do_group<2>(fb + 32 * HW_, off, dw, xw, doStore,
                        orow + (size_t)32 * OUTK * OUTK);
            break;
        case 3:
            do_group<3>(fb, off, dw, xw, doStore, orow);
            do_group<3>(fb + 32 * HW_, off, dw, xw, doStore,
                        orow + (size_t)32 * OUTK * OUTK);
            break;
        default:
            do_group<4>(fb, off, dw, xw, doStore, orow);
            do_group<4>(fb + 32 * HW_, off, dw, xw, doStore,
                        orow + (size_t)32 * OUTK * OUTK);
            break;
    }
}

extern "C" void kernel_launch(void* const* d_in, const int* in_sizes, int n_in,
                              void* d_out, int out_size) {
    const float* feat = (const float*)d_in[0];
    const float* rois = (const float*)d_in[1];
    if (n_in >= 2 && in_sizes[0] == R_ * 5) {  // defensive against input order
        feat = (const float*)d_in[1];
        rois = (const float*)d_in[0];
    }
    float* out = (float*)d_out;

    dim3 grid(OUTK, R_, C_ / CHUNK);
    roialign_kernel<<<grid, 256>>>(feat, rois, out);
}